// round 6
// baseline (speedup 1.0000x reference)
#include <cuda_runtime.h>
#include <math.h>

typedef unsigned long long ull;

#define BATCH 256
#define SEQT  512
#define EMBD  300
#define HID   150
#define G4    600   // 4*HID
#define NB    4     // batches per LSTM CTA
#define SMW   84    // Whh cols in smem (84 mod 32 = 20, gcd 4 -> conflict-free float4)
#define HS    152   // padded h/c/act stride (16B-aligned)

#define FMA2(d, a, b) asm("fma.rn.f32x2 %0, %1, %2, %3;" : "=l"(d) : "l"(a), "l"(b), "l"(d))

__device__ __forceinline__ float sig_f(float x)  { return __fdividef(1.f, 1.f + __expf(-x)); }
__device__ __forceinline__ float tanh_f(float x) { return 1.f - __fdividef(2.f, __expf(2.f * x) + 1.f); }

// ---------------- scratch (static device globals; no allocation) ----------------
__device__ float g_e [(size_t)BATCH*SEQT*EMBD];
__device__ float g_xp[(size_t)BATCH*SEQT*G4];
__device__ float g_sa[(size_t)BATCH*SEQT*HID];
__device__ float g_sb[(size_t)BATCH*SEQT*HID];
__device__ float g_hn[BATCH*HID];

// ---------------- embedding gather (x is int32 on device) ----------------
__global__ void embed_k(const int* __restrict__ x, const float* __restrict__ emb) {
    int idx = blockIdx.x * blockDim.x + threadIdx.x;
    const int total = BATCH * SEQT * (EMBD / 4);
    if (idx >= total) return;
    int bt = idx / (EMBD / 4);
    int d4 = (idx - bt * (EMBD / 4)) * 4;
    int row = x[bt];
    const float4 v = *(const float4*)(emb + (size_t)row * EMBD + d4);
    *(float4*)(g_e + (size_t)bt * EMBD + d4) = v;
}

// ---------------- x-projection GEMM: C[M,600] = A[M,K] @ W[600,K]^T + b1 + b2 ----------------
// 128x128 tile, 256 threads, 8x8 micro-tile (f32x2 along N).
// Register double-buffering: next k-tile loaded into regs while computing current.
__global__ void __launch_bounds__(256) gemm_xproj(
    const float* __restrict__ A, int K,
    const float* __restrict__ W,
    const float* __restrict__ b1,
    const float* __restrict__ b2,
    float* __restrict__ C) {
    __shared__ float As[16][132];
    __shared__ float Bs[16][132];
    const int tid = threadIdx.x;
    const int m0 = blockIdx.x * 128, n0 = blockIdx.y * 128;
    const int tx = tid & 15, ty = tid >> 4;
    const int lr = tid >> 1, lk = (tid & 1) * 8;

    ull acc2[8][4];
#pragma unroll
    for (int i = 0; i < 8; i++)
#pragma unroll
        for (int j = 0; j < 4; j++) acc2[i][j] = 0ull;

    const float* Ap = A + (size_t)(m0 + lr) * K;
    const int nrow = n0 + lr;
    const float* Wp = W + (size_t)nrow * K;
    const bool wok = nrow < G4;
    const int nt = (K + 15) / 16;

    float2 abuf[4], wbuf[4];
#pragma unroll
    for (int c = 0; c < 4; c++) {            // prologue: tile 0 -> regs
        int k = lk + 2 * c;
        abuf[c] = (k < K) ? *(const float2*)(Ap + k) : make_float2(0.f, 0.f);
        wbuf[c] = (wok && k < K) ? *(const float2*)(Wp + k) : make_float2(0.f, 0.f);
    }

    for (int kt = 0; kt < nt; kt++) {
#pragma unroll
        for (int c = 0; c < 4; c++) {        // regs -> smem (transposed)
            As[lk + 2 * c][lr]     = abuf[c].x;
            As[lk + 2 * c + 1][lr] = abuf[c].y;
            Bs[lk + 2 * c][lr]     = wbuf[c].x;
            Bs[lk + 2 * c + 1][lr] = wbuf[c].y;
        }
        __syncthreads();
        if (kt + 1 < nt) {                   // prefetch next tile into regs
            int kb = (kt + 1) * 16;
#pragma unroll
            for (int c = 0; c < 4; c++) {
                int k = kb + lk + 2 * c;
                abuf[c] = (k < K) ? *(const float2*)(Ap + k) : make_float2(0.f, 0.f);
                wbuf[c] = (wok && k < K) ? *(const float2*)(Wp + k) : make_float2(0.f, 0.f);
            }
        }
#pragma unroll
        for (int kk = 0; kk < 16; kk++) {
            float4 al = *(const float4*)&As[kk][ty * 4];
            float4 ah = *(const float4*)&As[kk][64 + ty * 4];
            ulonglong2 bl = *(const ulonglong2*)&Bs[kk][tx * 4];
            ulonglong2 bh = *(const ulonglong2*)&Bs[kk][64 + tx * 4];
            float a_s[8] = {al.x, al.y, al.z, al.w, ah.x, ah.y, ah.z, ah.w};
#pragma unroll
            for (int i = 0; i < 8; i++) {
                float2 t = make_float2(a_s[i], a_s[i]);
                ull ad = *(ull*)&t;
                FMA2(acc2[i][0], ad, bl.x);
                FMA2(acc2[i][1], ad, bl.y);
                FMA2(acc2[i][2], ad, bh.x);
                FMA2(acc2[i][3], ad, bh.y);
            }
        }
        __syncthreads();
    }
#pragma unroll
    for (int i = 0; i < 8; i++) {
        int m = m0 + ((i < 4) ? ty * 4 + i : 64 + ty * 4 + (i - 4));
        float* Cr = C + (size_t)m * G4;
#pragma unroll
        for (int j2 = 0; j2 < 4; j2++) {
            float2 p = *(float2*)&acc2[i][j2];
            int nn = n0 + ((j2 < 2) ? tx * 4 + 2 * j2 : 64 + tx * 4 + 2 * (j2 - 2));
            if (nn < G4)     Cr[nn]     = p.x + b1[nn]     + b2[nn];
            if (nn + 1 < G4) Cr[nn + 1] = p.y + b1[nn + 1] + b2[nn + 1];
        }
    }
}

// ---------------- LSTM layer: ONE CTA per 4 batch elements ----------------
// Thread r<600 owns gate row r for 4 batches. W cols [0,84) in smem;
// cols [84,150) streamed from L2 (Whh stays L2-resident) each step. No spills.
__global__ void __launch_bounds__(608, 1) lstm_k(
    const float* __restrict__ xp, const float* __restrict__ Whh,
    const int* __restrict__ lengths,
    float* __restrict__ seq_out, float* __restrict__ hn_out)
{
    extern __shared__ float sm[];
    float* Wsh = sm;                    // 600*SMW
    float* h_s = Wsh + 600 * SMW;       // NB*HS
    float* c_s = h_s + NB * HS;         // NB*HS
    float* act = c_s + NB * HS;         // NB*4*HS : [b][gate][j]

    const int tid = threadIdx.x;
    const int b0  = blockIdx.x * NB;

    for (int idx = tid; idx < 600 * SMW; idx += 608) {
        int r = idx / SMW, k = idx - r * SMW;
        Wsh[idx] = Whh[(size_t)r * 150 + k];
    }
    for (int idx = tid; idx < 2 * NB * HS; idx += 608) h_s[idx] = 0.f;  // h_s and c_s

    const int r = (tid < 600) ? tid : 0;
    const int gate = r / 150;
    const int jrow = r - gate * 150;
    const float* wp = Wsh + r * SMW;
    const float* wg = Whh + (size_t)r * 150;   // streamed cols [84,150)

    size_t xb[NB];
#pragma unroll
    for (int b = 0; b < NB; b++) xb[b] = ((size_t)(b0 + b) * SEQT) * G4 + r;

    int ub = 0, uj = 0, mylen = 0;
    if (tid < 600) {
        ub = tid / 150; uj = tid - ub * 150;
        mylen = lengths[b0 + ub];
    }

    __syncthreads();

    for (int t = 0; t < SEQT; t++) {
        if (tid < 600) {
            float xg[NB];
#pragma unroll
            for (int b = 0; b < NB; b++) xg[b] = xp[xb[b] + (size_t)t * G4];

            ull acc[NB];
#pragma unroll
            for (int b = 0; b < NB; b++) acc[b] = 0ull;

            // smem W part: cols [0,84)
#pragma unroll
            for (int g = 0; g < 21; g++) {
                const int k = 4 * g;
                ulonglong2 w2 = *(const ulonglong2*)(wp + k);
#pragma unroll
                for (int b = 0; b < NB; b++) {
                    ulonglong2 hv = *(const ulonglong2*)(h_s + b * HS + k);
                    FMA2(acc[b], w2.x, hv.x);
                    FMA2(acc[b], w2.y, hv.y);
                }
            }
            // streamed W part: cols [84,148)
#pragma unroll
            for (int g = 0; g < 16; g++) {
                const int k = SMW + 4 * g;
                ull w0 = *(const ull*)(wg + k);
                ull w1 = *(const ull*)(wg + k + 2);
#pragma unroll
                for (int b = 0; b < NB; b++) {
                    ulonglong2 hv = *(const ulonglong2*)(h_s + b * HS + k);
                    FMA2(acc[b], w0, hv.x);
                    FMA2(acc[b], w1, hv.y);
                }
            }
            {   // cols 148,149
                ull wt = *(const ull*)(wg + 148);
#pragma unroll
                for (int b = 0; b < NB; b++) {
                    ull hv = *(const ull*)(h_s + b * HS + 148);
                    FMA2(acc[b], wt, hv);
                }
            }
#pragma unroll
            for (int b = 0; b < NB; b++) {
                float2 f = *(float2*)&acc[b];
                float pre = f.x + f.y + xg[b];
                float v = (gate == 2) ? tanh_f(pre) : sig_f(pre);
                act[(b * 4 + gate) * HS + jrow] = v;
            }
        }
        __syncthreads();
        if (tid < 600) {
            float gi = act[(ub * 4 + 0) * HS + uj];
            float gf = act[(ub * 4 + 1) * HS + uj];
            float gg = act[(ub * 4 + 2) * HS + uj];
            float go = act[(ub * 4 + 3) * HS + uj];
            float c  = c_s[ub * HS + uj];
            float cn = fmaf(gf, c, gi * gg);
            float hv = go * tanh_f(cn);
            bool msk = t < mylen;
            seq_out[((size_t)(b0 + ub) * SEQT + t) * HID + uj] = msk ? hv : 0.f;
            if (msk) {
                c_s[ub * HS + uj] = cn;
                h_s[ub * HS + uj] = hv;
            }
        }
        __syncthreads();
    }

    if (tid < 600)
        hn_out[(b0 + ub) * HID + uj] = h_s[ub * HS + uj];
}

// ---------------- FC head ----------------
__global__ void fc_k(const float* __restrict__ hn, const float* __restrict__ w1,
                     const float* __restrict__ b1v, const float* __restrict__ w2,
                     const float* __restrict__ b2v, float* __restrict__ out) {
    __shared__ float red[256];
    int b = blockIdx.x, tid = threadIdx.x;
    float part = 0.f;
    if (tid < HID) {
        float acc = 0.f;
        const float* hr = hn + b * HID;
        const float* wrw = w1 + tid * HID;
        for (int k = 0; k < HID; k++) acc = fmaf(wrw[k], hr[k], acc);
        float z = fmaxf(acc + b1v[tid], 0.f);
        part = z * w2[tid];
    }
    red[tid] = part;
    __syncthreads();
    for (int s = 128; s > 0; s >>= 1) {
        if (tid < s) red[tid] += red[tid + s];
        __syncthreads();
    }
    if (tid == 0) out[b] = red[0] + b2v[0];
}

// ---------------- launch ----------------
extern "C" void kernel_launch(void* const* d_in, const int* in_sizes, int n_in,
                              void* d_out, int out_size) {
    const int* x   = (const int*)d_in[0];
    const int* len = (const int*)d_in[1];
    const float* emb = (const float*)d_in[2];
    const float *Wih[4], *Whh[4], *bih[4], *bhh[4];
    for (int l = 0; l < 4; l++) {
        Wih[l] = (const float*)d_in[3 + 4 * l];
        Whh[l] = (const float*)d_in[4 + 4 * l];
        bih[l] = (const float*)d_in[5 + 4 * l];
        bhh[l] = (const float*)d_in[6 + 4 * l];
    }
    const float* fc1w = (const float*)d_in[19];
    const float* fc1b = (const float*)d_in[20];
    const float* fc2w = (const float*)d_in[21];
    const float* fc2b = (const float*)d_in[22];
    float* out = (float*)d_out;

    float *pe, *pxp, *psa, *psb, *phn;
    cudaGetSymbolAddress((void**)&pe,  g_e);
    cudaGetSymbolAddress((void**)&pxp, g_xp);
    cudaGetSymbolAddress((void**)&psa, g_sa);
    cudaGetSymbolAddress((void**)&psb, g_sb);
    cudaGetSymbolAddress((void**)&phn, g_hn);

    const int SMEM = (600 * SMW + NB * HS * 2 + NB * 4 * HS) * 4;  // 216192 B
    cudaFuncSetAttribute(lstm_k, cudaFuncAttributeMaxDynamicSharedMemorySize, SMEM);

    embed_k<<<38400, 256>>>(x, emb);

    dim3 gg(1024, 5);
    gemm_xproj<<<gg, 256>>>(pe,  EMBD, Wih[0], bih[0], bhh[0], pxp);
    lstm_k<<<64, 608, SMEM>>>(pxp, Whh[0], len, psa, phn);

    gemm_xproj<<<gg, 256>>>(psa, HID,  Wih[1], bih[1], bhh[1], pxp);
    lstm_k<<<64, 608, SMEM>>>(pxp, Whh[1], len, psb, phn);

    gemm_xproj<<<gg, 256>>>(psb, HID,  Wih[2], bih[2], bhh[2], pxp);
    lstm_k<<<64, 608, SMEM>>>(pxp, Whh[2], len, psa, phn);

    gemm_xproj<<<gg, 256>>>(psa, HID,  Wih[3], bih[3], bhh[3], pxp);
    lstm_k<<<64, 608, SMEM>>>(pxp, Whh[3], len, psb, phn);

    fc_k<<<256, 256>>>(phn, fc1w, fc1b, fc2w, fc2b, out);
}

// round 7
// speedup vs baseline: 5.6955x; 5.6955x over previous
#include <cuda_runtime.h>
#include <math.h>

typedef unsigned long long ull;

#define BATCH 256
#define SEQT  512
#define EMBD  300
#define HID   150
#define G4    600   // 4*HID
#define SMW   92    // Whh cols in smem (92 mod 32 = 28, gcd 4 -> conflict-free float4)
#define NRW   58    // Whh cols in registers = 29 u64
#define HS    152   // padded h/c/act stride (16B-aligned)

#define FMA2(d, a, b) asm("fma.rn.f32x2 %0, %1, %2, %3;" : "=l"(d) : "l"(a), "l"(b), "l"(d))

__device__ __forceinline__ float sig_f(float x)  { return __fdividef(1.f, 1.f + __expf(-x)); }
__device__ __forceinline__ float tanh_f(float x) { return 1.f - __fdividef(2.f, __expf(2.f * x) + 1.f); }

// ---------------- scratch (static device globals; no allocation) ----------------
__device__ float g_e [(size_t)BATCH*SEQT*EMBD];
__device__ float g_xp[(size_t)BATCH*SEQT*G4];
__device__ float g_sa[(size_t)BATCH*SEQT*HID];
__device__ float g_sb[(size_t)BATCH*SEQT*HID];
__device__ float g_hn[BATCH*HID];

// ---------------- embedding gather (x is int32 on device) ----------------
__global__ void embed_k(const int* __restrict__ x, const float* __restrict__ emb) {
    int idx = blockIdx.x * blockDim.x + threadIdx.x;
    const int total = BATCH * SEQT * (EMBD / 4);
    if (idx >= total) return;
    int bt = idx / (EMBD / 4);
    int d4 = (idx - bt * (EMBD / 4)) * 4;
    int row = x[bt];
    const float4 v = *(const float4*)(emb + (size_t)row * EMBD + d4);
    *(float4*)(g_e + (size_t)bt * EMBD + d4) = v;
}

// ---------------- x-projection GEMM (round-5 version: best measured) ----------------
__global__ void __launch_bounds__(256) gemm_xproj(
    const float* __restrict__ A, int K,
    const float* __restrict__ W,
    const float* __restrict__ b1,
    const float* __restrict__ b2,
    float* __restrict__ C) {
    __shared__ float As[16][132];
    __shared__ float Bs[16][132];
    const int tid = threadIdx.x;
    const int m0 = blockIdx.x * 128, n0 = blockIdx.y * 128;
    const int tx = tid & 15, ty = tid >> 4;
    const int lr = tid >> 1, lk = (tid & 1) * 8;

    ull acc2[8][4];
#pragma unroll
    for (int i = 0; i < 8; i++)
#pragma unroll
        for (int j = 0; j < 4; j++) acc2[i][j] = 0ull;

    const float* Ap = A + (size_t)(m0 + lr) * K;
    const int nrow = n0 + lr;
    const float* Wp = W + (size_t)nrow * K;
    const bool wok = nrow < G4;
    const int nt = (K + 15) / 16;

    for (int kt = 0; kt < nt; kt++) {
        const int k0 = kt * 16;
#pragma unroll
        for (int c = 0; c < 4; c++) {
            int k = k0 + lk + 2 * c;
            float2 av = (k < K) ? *(const float2*)(Ap + k) : make_float2(0.f, 0.f);
            float2 wv = (wok && k < K) ? *(const float2*)(Wp + k) : make_float2(0.f, 0.f);
            As[lk + 2 * c][lr]     = av.x;
            As[lk + 2 * c + 1][lr] = av.y;
            Bs[lk + 2 * c][lr]     = wv.x;
            Bs[lk + 2 * c + 1][lr] = wv.y;
        }
        __syncthreads();
#pragma unroll
        for (int kk = 0; kk < 16; kk++) {
            float4 al = *(const float4*)&As[kk][ty * 4];
            float4 ah = *(const float4*)&As[kk][64 + ty * 4];
            ulonglong2 bl = *(const ulonglong2*)&Bs[kk][tx * 4];
            ulonglong2 bh = *(const ulonglong2*)&Bs[kk][64 + tx * 4];
            float a_s[8] = {al.x, al.y, al.z, al.w, ah.x, ah.y, ah.z, ah.w};
#pragma unroll
            for (int i = 0; i < 8; i++) {
                float2 t = make_float2(a_s[i], a_s[i]);
                ull ad = *(ull*)&t;
                FMA2(acc2[i][0], ad, bl.x);
                FMA2(acc2[i][1], ad, bl.y);
                FMA2(acc2[i][2], ad, bh.x);
                FMA2(acc2[i][3], ad, bh.y);
            }
        }
        __syncthreads();
    }
#pragma unroll
    for (int i = 0; i < 8; i++) {
        int m = m0 + ((i < 4) ? ty * 4 + i : 64 + ty * 4 + (i - 4));
        float* Cr = C + (size_t)m * G4;
#pragma unroll
        for (int j2 = 0; j2 < 4; j2++) {
            float2 p = *(float2*)&acc2[i][j2];
            int nn = n0 + ((j2 < 2) ? tx * 4 + 2 * j2 : 64 + tx * 4 + 2 * (j2 - 2));
            if (nn < G4)     Cr[nn]     = p.x + b1[nn]     + b2[nn];
            if (nn + 1 < G4) Cr[nn + 1] = p.y + b1[nn + 1] + b2[nn + 1];
        }
    }
}

// ---------------- LSTM layer: ONE CTA per 2 batch elements ----------------
// Thread r<600 owns gate row r for both batches. W cols [0,92) smem (220.8KB),
// cols [92,150) in 29 u64 registers. NO global W traffic inside the loop.
__global__ void __launch_bounds__(608, 1) lstm_k(
    const float* __restrict__ xp, const float* __restrict__ Whh,
    const int* __restrict__ lengths,
    float* __restrict__ seq_out, float* __restrict__ hn_out)
{
    extern __shared__ float sm[];
    float* Wsh = sm;                    // 600*SMW
    float* h_s = Wsh + 600 * SMW;       // 2*HS
    float* c_s = h_s + 2 * HS;          // 2*HS
    float* act = c_s + 2 * HS;          // 8*HS : [b][gate][j]

    const int tid = threadIdx.x;
    const int b0  = blockIdx.x * 2;

    for (int idx = tid; idx < 600 * SMW; idx += 608) {
        int r = idx / SMW, k = idx - r * SMW;
        Wsh[idx] = Whh[(size_t)r * 150 + k];
    }
    for (int idx = tid; idx < 4 * HS; idx += 608) h_s[idx] = 0.f;  // h_s + c_s

    const int r = (tid < 600) ? tid : 0;
    // register part: cols 92..149 as 29 packed u64 pairs (8B-aligned: 150r+92 even)
    ull wr2[29];
    const float* wg = Whh + (size_t)r * 150 + SMW;
#pragma unroll
    for (int i = 0; i < 29; i++)
        wr2[i] = (tid < 600) ? *(const ull*)(wg + 2 * i) : 0ull;

    const int gate = r / 150;
    const int jrow = r - gate * 150;
    const float* wp = Wsh + r * SMW;
    const size_t xbA = ((size_t)b0 * SEQT) * G4 + r;
    const size_t xbB = ((size_t)(b0 + 1) * SEQT) * G4 + r;

    int ub = 0, uj = 0, mylen = 0;
    if (tid < 300) {
        ub = tid / 150; uj = tid - ub * 150;
        mylen = lengths[b0 + ub];
    }

    __syncthreads();

    for (int t = 0; t < SEQT; t++) {
        if (tid < 600) {
            float xgA = xp[xbA + (size_t)t * G4];
            float xgB = xp[xbB + (size_t)t * G4];
            ull accA = 0ull, accB = 0ull;
            const float* hA = h_s;
            const float* hB = h_s + HS;
            // smem W: cols [0,92)
#pragma unroll
            for (int g = 0; g < 23; g++) {
                const int k = 4 * g;
                ulonglong2 w2 = *(const ulonglong2*)(wp + k);
                ulonglong2 a2 = *(const ulonglong2*)(hA + k);
                ulonglong2 b2 = *(const ulonglong2*)(hB + k);
                FMA2(accA, w2.x, a2.x); FMA2(accA, w2.y, a2.y);
                FMA2(accB, w2.x, b2.x); FMA2(accB, w2.y, b2.y);
            }
            // register W: cols [92,148)
#pragma unroll
            for (int c = 0; c < 14; c++) {
                const int k = SMW + 4 * c;
                ulonglong2 a2 = *(const ulonglong2*)(hA + k);
                ulonglong2 b2 = *(const ulonglong2*)(hB + k);
                FMA2(accA, wr2[2 * c], a2.x); FMA2(accA, wr2[2 * c + 1], a2.y);
                FMA2(accB, wr2[2 * c], b2.x); FMA2(accB, wr2[2 * c + 1], b2.y);
            }
            {   // cols 148,149
                ull a1 = *(const ull*)(hA + 148);
                ull b1 = *(const ull*)(hB + 148);
                FMA2(accA, wr2[28], a1); FMA2(accB, wr2[28], b1);
            }
            float2 fA = *(float2*)&accA;
            float2 fB = *(float2*)&accB;
            float preA = fA.x + fA.y + xgA;
            float preB = fB.x + fB.y + xgB;
            float vA, vB;
            if (gate == 2) { vA = tanh_f(preA); vB = tanh_f(preB); }
            else           { vA = sig_f(preA);  vB = sig_f(preB);  }
            act[(0 * 4 + gate) * HS + jrow] = vA;
            act[(1 * 4 + gate) * HS + jrow] = vB;
        }
        __syncthreads();
        if (tid < 300) {
            float gi = act[(ub * 4 + 0) * HS + uj];
            float gf = act[(ub * 4 + 1) * HS + uj];
            float gg = act[(ub * 4 + 2) * HS + uj];
            float go = act[(ub * 4 + 3) * HS + uj];
            float c  = c_s[ub * HS + uj];
            float cn = fmaf(gf, c, gi * gg);
            float hv = go * tanh_f(cn);
            bool msk = t < mylen;
            seq_out[((size_t)(b0 + ub) * SEQT + t) * HID + uj] = msk ? hv : 0.f;
            if (msk) {
                c_s[ub * HS + uj] = cn;
                h_s[ub * HS + uj] = hv;
            }
        }
        __syncthreads();
    }

    if (tid < 300)
        hn_out[(b0 + ub) * HID + uj] = h_s[ub * HS + uj];
}

// ---------------- FC head ----------------
__global__ void fc_k(const float* __restrict__ hn, const float* __restrict__ w1,
                     const float* __restrict__ b1v, const float* __restrict__ w2,
                     const float* __restrict__ b2v, float* __restrict__ out) {
    __shared__ float red[256];
    int b = blockIdx.x, tid = threadIdx.x;
    float part = 0.f;
    if (tid < HID) {
        float acc = 0.f;
        const float* hr = hn + b * HID;
        const float* wrw = w1 + tid * HID;
        for (int k = 0; k < HID; k++) acc = fmaf(wrw[k], hr[k], acc);
        float z = fmaxf(acc + b1v[tid], 0.f);
        part = z * w2[tid];
    }
    red[tid] = part;
    __syncthreads();
    for (int s = 128; s > 0; s >>= 1) {
        if (tid < s) red[tid] += red[tid + s];
        __syncthreads();
    }
    if (tid == 0) out[b] = red[0] + b2v[0];
}

// ---------------- launch ----------------
extern "C" void kernel_launch(void* const* d_in, const int* in_sizes, int n_in,
                              void* d_out, int out_size) {
    const int* x   = (const int*)d_in[0];
    const int* len = (const int*)d_in[1];
    const float* emb = (const float*)d_in[2];
    const float *Wih[4], *Whh[4], *bih[4], *bhh[4];
    for (int l = 0; l < 4; l++) {
        Wih[l] = (const float*)d_in[3 + 4 * l];
        Whh[l] = (const float*)d_in[4 + 4 * l];
        bih[l] = (const float*)d_in[5 + 4 * l];
        bhh[l] = (const float*)d_in[6 + 4 * l];
    }
    const float* fc1w = (const float*)d_in[19];
    const float* fc1b = (const float*)d_in[20];
    const float* fc2w = (const float*)d_in[21];
    const float* fc2b = (const float*)d_in[22];
    float* out = (float*)d_out;

    float *pe, *pxp, *psa, *psb, *phn;
    cudaGetSymbolAddress((void**)&pe,  g_e);
    cudaGetSymbolAddress((void**)&pxp, g_xp);
    cudaGetSymbolAddress((void**)&psa, g_sa);
    cudaGetSymbolAddress((void**)&psb, g_sb);
    cudaGetSymbolAddress((void**)&phn, g_hn);

    const int SMEM = (600 * SMW + 2 * HS + 2 * HS + 8 * HS) * 4;  // 228096 B
    cudaFuncSetAttribute(lstm_k, cudaFuncAttributeMaxDynamicSharedMemorySize, SMEM);

    embed_k<<<38400, 256>>>(x, emb);

    dim3 gg(1024, 5);
    gemm_xproj<<<gg, 256>>>(pe,  EMBD, Wih[0], bih[0], bhh[0], pxp);
    lstm_k<<<128, 608, SMEM>>>(pxp, Whh[0], len, psa, phn);

    gemm_xproj<<<gg, 256>>>(psa, HID,  Wih[1], bih[1], bhh[1], pxp);
    lstm_k<<<128, 608, SMEM>>>(pxp, Whh[1], len, psb, phn);

    gemm_xproj<<<gg, 256>>>(psb, HID,  Wih[2], bih[2], bhh[2], pxp);
    lstm_k<<<128, 608, SMEM>>>(pxp, Whh[2], len, psa, phn);

    gemm_xproj<<<gg, 256>>>(psa, HID,  Wih[3], bih[3], bhh[3], pxp);
    lstm_k<<<128, 608, SMEM>>>(pxp, Whh[3], len, psb, phn);

    fc_k<<<256, 256>>>(phn, fc1w, fc1b, fc2w, fc2b, out);
}